// round 4
// baseline (speedup 1.0000x reference)
#include <cuda_runtime.h>
#include <cuda_fp16.h>
#include <math.h>

#define MAXN 100000
#define MAXE 1600000
#define HDIM 64
#define SCAN_TILE 4096

// ---------------- device scratch (no allocations allowed) ----------------
__device__ int    g_is64;
__device__ int    g_row [MAXE];
__device__ int    g_cole[MAXE];
__device__ int    g_srcs[MAXE];
__device__ int    g_degi[MAXN];
__device__ int    g_off [MAXN];
__device__ int    g_cur [MAXN];
__device__ int    g_bsum[64];
__device__ float  g_dinv[MAXN];
__device__ __half g_yh[(size_t)MAXN * HDIM];   // dinv-scaled xW, fp16
__device__ float  g_h [(size_t)MAXN * HDIM];   // layer activations, fp32

// ---------------- dtype detection (int32 vs int64 edge_index) ------------
__global__ void detect_kernel(const int* __restrict__ ei) {
    if (threadIdx.x == 0 && blockIdx.x == 0) {
        int is64 = 1;
        for (int i = 1; i < 128; i += 2)
            if (ei[i] != 0) { is64 = 0; break; }
        g_is64 = is64;
    }
}

__global__ void zero_deg(int N) {
    int i = blockIdx.x * blockDim.x + threadIdx.x;
    if (i < N) g_degi[i] = 0;
}

__global__ void convert_kernel(const void* __restrict__ ei, int E) {
    int e = blockIdx.x * blockDim.x + threadIdx.x;
    if (e >= E) return;
    int r, c;
    if (g_is64) {
        const long long* p = (const long long*)ei;
        r = (int)p[e]; c = (int)p[e + E];
    } else {
        const int* p = (const int*)ei;
        r = p[e]; c = p[e + E];
    }
    g_row[e] = r;
    g_cole[e] = c;
    atomicAdd(&g_degi[c], 1);
}

// ---------------- multi-block exclusive scan ------------------------------
__global__ void scan_pass1(int N) {
    __shared__ int warpsum[32];
    int lane = threadIdx.x & 31, wid = threadIdx.x >> 5;
    int idx = blockIdx.x * SCAN_TILE + threadIdx.x * 4;

    int4 v = make_int4(0, 0, 0, 0);
    if (idx + 3 < N) v = *(const int4*)(g_degi + idx);
    else {
        if (idx     < N) v.x = g_degi[idx];
        if (idx + 1 < N) v.y = g_degi[idx + 1];
        if (idx + 2 < N) v.z = g_degi[idx + 2];
        if (idx + 3 < N) v.w = g_degi[idx + 3];
    }
    int s0 = v.x, s1 = s0 + v.y, s2 = s1 + v.z, s3 = s2 + v.w;
    int sc = s3;
    #pragma unroll
    for (int o = 1; o < 32; o <<= 1) {
        int t = __shfl_up_sync(0xffffffffu, sc, o);
        if (lane >= o) sc += t;
    }
    if (lane == 31) warpsum[wid] = sc;
    __syncthreads();
    if (wid == 0) {
        int ws = warpsum[lane];
        int wsc = ws;
        #pragma unroll
        for (int o = 1; o < 32; o <<= 1) {
            int t = __shfl_up_sync(0xffffffffu, wsc, o);
            if (lane >= o) wsc += t;
        }
        warpsum[lane] = wsc - ws;
        if (lane == 31) g_bsum[blockIdx.x] = wsc;
    }
    __syncthreads();
    int carry = warpsum[wid] + (sc - s3);
    if (idx     < N) g_off[idx]     = carry;
    if (idx + 1 < N) g_off[idx + 1] = carry + s0;
    if (idx + 2 < N) g_off[idx + 2] = carry + s1;
    if (idx + 3 < N) g_off[idx + 3] = carry + s2;
}

__global__ void scan_pass2(int nblk) {
    int lane = threadIdx.x;  // 64 threads
    __shared__ int sh[64];
    int v = (lane < nblk) ? g_bsum[lane] : 0;
    sh[lane] = v;
    __syncthreads();
    int acc = v;
    for (int o = 1; o < 64; o <<= 1) {
        int t = (lane >= o) ? sh[lane - o] : 0;
        __syncthreads();
        acc += t;
        sh[lane] = acc;
        __syncthreads();
    }
    if (lane < nblk) g_bsum[lane] = acc - v;
}

__global__ void scan_pass3(int N) {
    int idx = (blockIdx.x * blockDim.x + threadIdx.x) * 4;
    if (idx >= N) return;
    int add = g_bsum[idx / SCAN_TILE];
    if (idx + 3 < N) {
        int4 v = *(const int4*)(g_off + idx);
        v.x += add; v.y += add; v.z += add; v.w += add;
        *(int4*)(g_off + idx) = v;
        *(int4*)(g_cur + idx) = v;
    } else {
        for (int k = 0; k < 4 && idx + k < N; k++) {
            int v = g_off[idx + k] + add;
            g_off[idx + k] = v;
            g_cur[idx + k] = v;
        }
    }
}

__global__ void place_kernel(int E) {
    int e = blockIdx.x * blockDim.x + threadIdx.x;
    if (e >= E) return;
    int c = g_cole[e];
    int pos = atomicAdd(&g_cur[c], 1);
    g_srcs[pos] = g_row[e];
}

__global__ void dinv_kernel(int N) {
    int i = blockIdx.x * blockDim.x + threadIdx.x;
    if (i < N) g_dinv[i] = rsqrtf((float)(g_degi[i] + 1));
}

// ---------------- GEMM: Yh = fp16((X @ W) * dinv) --------------------------
// Block tile 128 rows x 64 cols, 128 threads, 8x8 per thread.
template<int K, bool X_FROM_GH>
__global__ void __launch_bounds__(128, 4)
gemm_scale(const float* __restrict__ Xin, const float* __restrict__ W, int N) {
    const float* __restrict__ X = X_FROM_GH ? g_h : Xin;
    __shared__ float Xs[16][128];
    __shared__ float Ws[16][64];

    int tid = threadIdx.x;            // 0..127
    int ty = tid >> 3;                // 0..15 -> rows ty*8..+7
    int tx = tid & 7;                 // 0..7  -> cols tx*8..+7
    int row0 = blockIdx.x * 128;

    float acc[8][8] = {};

    for (int kc = 0; kc < K; kc += 16) {
        // A: thread tid loads all 16 k-values of row (row0 + tid)
        int grow = row0 + tid;
        if (grow < N) {
            const float* xp = X + (size_t)grow * K + kc;
            #pragma unroll
            for (int q = 0; q < 4; q++) {
                float4 v = *(const float4*)(xp + q * 4);
                Xs[q * 4 + 0][tid] = v.x;
                Xs[q * 4 + 1][tid] = v.y;
                Xs[q * 4 + 2][tid] = v.z;
                Xs[q * 4 + 3][tid] = v.w;
            }
        } else {
            #pragma unroll
            for (int q = 0; q < 16; q++) Xs[q][tid] = 0.f;
        }
        // B: 16x64, 2 float4 per thread
        {
            int wr = tid >> 3;
            int wc = (tid & 7) * 8;
            *(float4*)&Ws[wr][wc]     = *(const float4*)(W + (size_t)(kc + wr) * 64 + wc);
            *(float4*)&Ws[wr][wc + 4] = *(const float4*)(W + (size_t)(kc + wr) * 64 + wc + 4);
        }
        __syncthreads();

        #pragma unroll
        for (int k = 0; k < 16; k++) {
            float a[8], b[8];
            *(float4*)&a[0] = *(const float4*)&Xs[k][ty * 8];
            *(float4*)&a[4] = *(const float4*)&Xs[k][ty * 8 + 4];
            *(float4*)&b[0] = *(const float4*)&Ws[k][tx * 8];
            *(float4*)&b[4] = *(const float4*)&Ws[k][tx * 8 + 4];
            #pragma unroll
            for (int i = 0; i < 8; i++)
                #pragma unroll
                for (int j = 0; j < 8; j++)
                    acc[i][j] = fmaf(a[i], b[j], acc[i][j]);
        }
        __syncthreads();
    }

    #pragma unroll
    for (int i = 0; i < 8; i++) {
        int r = row0 + ty * 8 + i;
        if (r < N) {
            float s = g_dinv[r];
            __half2 p[4];
            #pragma unroll
            for (int j = 0; j < 4; j++)
                p[j] = __floats2half2_rn(acc[i][2 * j] * s, acc[i][2 * j + 1] * s);
            *(uint4*)(g_yh + (size_t)r * 64 + tx * 8) = *(uint4*)p;
        }
    }
}

// ---------------- warp-per-node aggregation (no atomics, fp16 reads) -------
template<bool FINAL>
__global__ void aggregate_kernel(const float* __restrict__ bias,
                                 const float* __restrict__ Wfc,
                                 const float* __restrict__ bfc,
                                 float* __restrict__ out, int N) {
    int node = blockIdx.x * 8 + (threadIdx.x >> 5);
    if (node >= N) return;
    int lane = threadIdx.x & 31;

    const __half2* yb = (const __half2*)g_yh;   // 32 half2 per row

    int beg = g_off[node];
    int cnt = g_degi[node];

    float2 acc = __half22float2(yb[(size_t)node * 32 + lane]);  // self loop

    int i = 0;
    for (; i + 3 < cnt; i += 4) {
        int s0 = __ldg(&g_srcs[beg + i]);
        int s1 = __ldg(&g_srcs[beg + i + 1]);
        int s2 = __ldg(&g_srcs[beg + i + 2]);
        int s3 = __ldg(&g_srcs[beg + i + 3]);
        float2 v0 = __half22float2(yb[(size_t)s0 * 32 + lane]);
        float2 v1 = __half22float2(yb[(size_t)s1 * 32 + lane]);
        float2 v2 = __half22float2(yb[(size_t)s2 * 32 + lane]);
        float2 v3 = __half22float2(yb[(size_t)s3 * 32 + lane]);
        acc.x += (v0.x + v1.x) + (v2.x + v3.x);
        acc.y += (v0.y + v1.y) + (v2.y + v3.y);
    }
    for (; i < cnt; i++) {
        int s0 = __ldg(&g_srcs[beg + i]);
        float2 v0 = __half22float2(yb[(size_t)s0 * 32 + lane]);
        acc.x += v0.x;
        acc.y += v0.y;
    }

    float dv = g_dinv[node];
    float hx = fmaxf(fmaf(acc.x, dv, __ldg(&bias[lane * 2])), 0.f);
    float hy = fmaxf(fmaf(acc.y, dv, __ldg(&bias[lane * 2 + 1])), 0.f);

    if (!FINAL) {
        *(float2*)(g_h + (size_t)node * 64 + lane * 2) = make_float2(hx, hy);
    } else {
        float v = hx * __ldg(&Wfc[lane * 2]) + hy * __ldg(&Wfc[lane * 2 + 1]);
        #pragma unroll
        for (int o = 16; o; o >>= 1)
            v += __shfl_down_sync(0xffffffffu, v, o);
        if (lane == 0) {
            float z = v + __ldg(&bfc[0]);
            out[node] = 1.0f / (1.0f + expf(-z));
        }
    }
}

// ---------------- launch ----------------------------------------------------
extern "C" void kernel_launch(void* const* d_in, const int* in_sizes, int n_in,
                              void* d_out, int out_size) {
    const float* x   = (const float*)d_in[0];
    const void*  ei  = d_in[1];
    const float* W1  = (const float*)d_in[2];
    const float* b1  = (const float*)d_in[3];
    const float* W2  = (const float*)d_in[4];
    const float* b2  = (const float*)d_in[5];
    const float* Wfc = (const float*)d_in[6];
    const float* bfc = (const float*)d_in[7];
    float* out = (float*)d_out;

    int N = in_sizes[0] / 128;
    int E = in_sizes[1] / 2;
    if (N > MAXN) N = MAXN;
    if (E > MAXE) E = MAXE;

    const int TB = 256;
    int nb_N  = (N + TB - 1) / TB;
    int nb_E  = (E + TB - 1) / TB;
    int nb_GM = (N + 127) / 128;
    int nb_AG = (N + 7) / 8;
    int nblk  = (N + SCAN_TILE - 1) / SCAN_TILE;
    int nb_P3 = (N + TB * 4 - 1) / (TB * 4);

    detect_kernel<<<1, 32>>>((const int*)ei);
    zero_deg<<<nb_N, TB>>>(N);
    convert_kernel<<<nb_E, TB>>>(ei, E);
    scan_pass1<<<nblk, 1024>>>(N);
    scan_pass2<<<1, 64>>>(nblk);
    scan_pass3<<<nb_P3, TB>>>(N);
    place_kernel<<<nb_E, TB>>>(E);
    dinv_kernel<<<nb_N, TB>>>(N);

    // layer 1
    gemm_scale<128, false><<<nb_GM, 128>>>(x, W1, N);
    aggregate_kernel<false><<<nb_AG, 256>>>(b1, nullptr, nullptr, nullptr, N);

    // layer 2
    gemm_scale<64, true><<<nb_GM, 128>>>(nullptr, W2, N);
    aggregate_kernel<true><<<nb_AG, 256>>>(b2, Wfc, bfc, out, N);
}

// round 5
// speedup vs baseline: 1.1359x; 1.1359x over previous
#include <cuda_runtime.h>
#include <cuda_fp16.h>
#include <math.h>

#define MAXN 100000
#define MAXE 1600000
#define HDIM 64
#define SCAN_TILE 4096

// ---------------- device scratch (no allocations allowed) ----------------
__device__ int    g_is64;
__device__ int    g_row [MAXE];
__device__ int    g_cole[MAXE];
__device__ int    g_srcs[MAXE];
__device__ int    g_degi[MAXN];
__device__ int    g_off [MAXN];
__device__ int    g_cur [MAXN];
__device__ int    g_bsum[64];
__device__ float  g_dinv[MAXN];
__device__ __half g_yh[(size_t)MAXN * HDIM];   // dinv-scaled xW, fp16
__device__ float  g_h [(size_t)MAXN * HDIM];   // layer activations, fp32

// ---------------- dtype detection (int32 vs int64 edge_index) ------------
__global__ void detect_kernel(const int* __restrict__ ei) {
    if (threadIdx.x == 0 && blockIdx.x == 0) {
        int is64 = 1;
        for (int i = 1; i < 128; i += 2)
            if (ei[i] != 0) { is64 = 0; break; }
        g_is64 = is64;
    }
}

__global__ void zero_deg(int N) {
    int i = blockIdx.x * blockDim.x + threadIdx.x;
    if (i < N) g_degi[i] = 0;
}

__global__ void convert_kernel(const void* __restrict__ ei, int E) {
    int e = blockIdx.x * blockDim.x + threadIdx.x;
    if (e >= E) return;
    int r, c;
    if (g_is64) {
        const long long* p = (const long long*)ei;
        r = (int)p[e]; c = (int)p[e + E];
    } else {
        const int* p = (const int*)ei;
        r = p[e]; c = p[e + E];
    }
    g_row[e] = r;
    g_cole[e] = c;
    atomicAdd(&g_degi[c], 1);
}

// ---------------- multi-block exclusive scan ------------------------------
__global__ void scan_pass1(int N) {
    __shared__ int warpsum[32];
    int lane = threadIdx.x & 31, wid = threadIdx.x >> 5;
    int idx = blockIdx.x * SCAN_TILE + threadIdx.x * 4;

    int4 v = make_int4(0, 0, 0, 0);
    if (idx + 3 < N) v = *(const int4*)(g_degi + idx);
    else {
        if (idx     < N) v.x = g_degi[idx];
        if (idx + 1 < N) v.y = g_degi[idx + 1];
        if (idx + 2 < N) v.z = g_degi[idx + 2];
        if (idx + 3 < N) v.w = g_degi[idx + 3];
    }
    int s0 = v.x, s1 = s0 + v.y, s2 = s1 + v.z, s3 = s2 + v.w;
    int sc = s3;
    #pragma unroll
    for (int o = 1; o < 32; o <<= 1) {
        int t = __shfl_up_sync(0xffffffffu, sc, o);
        if (lane >= o) sc += t;
    }
    if (lane == 31) warpsum[wid] = sc;
    __syncthreads();
    if (wid == 0) {
        int ws = warpsum[lane];
        int wsc = ws;
        #pragma unroll
        for (int o = 1; o < 32; o <<= 1) {
            int t = __shfl_up_sync(0xffffffffu, wsc, o);
            if (lane >= o) wsc += t;
        }
        warpsum[lane] = wsc - ws;
        if (lane == 31) g_bsum[blockIdx.x] = wsc;
    }
    __syncthreads();
    int carry = warpsum[wid] + (sc - s3);
    if (idx     < N) g_off[idx]     = carry;
    if (idx + 1 < N) g_off[idx + 1] = carry + s0;
    if (idx + 2 < N) g_off[idx + 2] = carry + s1;
    if (idx + 3 < N) g_off[idx + 3] = carry + s2;
}

__global__ void scan_pass2(int nblk) {
    int lane = threadIdx.x;  // 64 threads
    __shared__ int sh[64];
    int v = (lane < nblk) ? g_bsum[lane] : 0;
    sh[lane] = v;
    __syncthreads();
    int acc = v;
    for (int o = 1; o < 64; o <<= 1) {
        int t = (lane >= o) ? sh[lane - o] : 0;
        __syncthreads();
        acc += t;
        sh[lane] = acc;
        __syncthreads();
    }
    if (lane < nblk) g_bsum[lane] = acc - v;
}

__global__ void scan_pass3(int N) {
    int idx = (blockIdx.x * blockDim.x + threadIdx.x) * 4;
    if (idx >= N) return;
    int add = g_bsum[idx / SCAN_TILE];
    if (idx + 3 < N) {
        int4 v = *(const int4*)(g_off + idx);
        v.x += add; v.y += add; v.z += add; v.w += add;
        *(int4*)(g_off + idx) = v;
        *(int4*)(g_cur + idx) = v;
    } else {
        for (int k = 0; k < 4 && idx + k < N; k++) {
            int v = g_off[idx + k] + add;
            g_off[idx + k] = v;
            g_cur[idx + k] = v;
        }
    }
}

__global__ void place_kernel(int E) {
    int e = blockIdx.x * blockDim.x + threadIdx.x;
    if (e >= E) return;
    int c = g_cole[e];
    int pos = atomicAdd(&g_cur[c], 1);
    g_srcs[pos] = g_row[e];
}

__global__ void dinv_kernel(int N) {
    int i = blockIdx.x * blockDim.x + threadIdx.x;
    if (i < N) g_dinv[i] = rsqrtf((float)(g_degi[i] + 1));
}

// ---------------- GEMM: Yh = fp16((X @ W) * dinv) --------------------------
// R3-proven shape: X [N,K] row-major, W [K,64]. Block 64x64, 256 threads, 4x4.
template<int K, bool X_FROM_GH>
__global__ void gemm_scale(const float* __restrict__ Xin,
                           const float* __restrict__ W, int N) {
    const float* __restrict__ X = X_FROM_GH ? g_h : Xin;
    __shared__ float Xs[16][64];
    __shared__ float Ws[16][64];

    int tid = threadIdx.x;
    int ty = tid >> 4;
    int tx = tid & 15;
    int row0 = blockIdx.x * 64;

    float acc[4][4] = {};

    int lr  = tid >> 2;
    int lkq = (tid & 3) << 2;
    int wkr = tid >> 4;
    int wcq = (tid & 15) << 2;

    for (int kc = 0; kc < K; kc += 16) {
        float4 xv = make_float4(0.f, 0.f, 0.f, 0.f);
        int grow = row0 + lr;
        if (grow < N)
            xv = *(const float4*)(X + (size_t)grow * K + kc + lkq);
        Xs[lkq + 0][lr] = xv.x;
        Xs[lkq + 1][lr] = xv.y;
        Xs[lkq + 2][lr] = xv.z;
        Xs[lkq + 3][lr] = xv.w;

        *(float4*)&Ws[wkr][wcq] =
            *(const float4*)(W + (size_t)(kc + wkr) * 64 + wcq);
        __syncthreads();

        #pragma unroll
        for (int k = 0; k < 16; k++) {
            float4 a = *(const float4*)&Xs[k][ty << 2];
            float4 b = *(const float4*)&Ws[k][tx << 2];
            float av[4] = {a.x, a.y, a.z, a.w};
            float bv[4] = {b.x, b.y, b.z, b.w};
            #pragma unroll
            for (int i = 0; i < 4; i++)
                #pragma unroll
                for (int j = 0; j < 4; j++)
                    acc[i][j] = fmaf(av[i], bv[j], acc[i][j]);
        }
        __syncthreads();
    }

    #pragma unroll
    for (int i = 0; i < 4; i++) {
        int r = row0 + (ty << 2) + i;
        if (r < N) {
            float s = g_dinv[r];
            __half2 p0 = __floats2half2_rn(acc[i][0] * s, acc[i][1] * s);
            __half2 p1 = __floats2half2_rn(acc[i][2] * s, acc[i][3] * s);
            *(uint2*)(g_yh + (size_t)r * 64 + (tx << 2)) =
                make_uint2(*(unsigned*)&p0, *(unsigned*)&p1);
        }
    }
}

// ---------------- warp-per-node aggregation (no atomics, fp16 reads) -------
template<bool FINAL>
__global__ void aggregate_kernel(const float* __restrict__ bias,
                                 const float* __restrict__ Wfc,
                                 const float* __restrict__ bfc,
                                 float* __restrict__ out, int N) {
    int node = blockIdx.x * 8 + (threadIdx.x >> 5);
    if (node >= N) return;
    int lane = threadIdx.x & 31;

    const __half2* yb = (const __half2*)g_yh;   // 32 half2 per row

    int beg = g_off[node];
    int cnt = g_degi[node];

    float2 acc = __half22float2(yb[(size_t)node * 32 + lane]);  // self loop

    int i = 0;
    for (; i + 3 < cnt; i += 4) {
        int s0 = __ldg(&g_srcs[beg + i]);
        int s1 = __ldg(&g_srcs[beg + i + 1]);
        int s2 = __ldg(&g_srcs[beg + i + 2]);
        int s3 = __ldg(&g_srcs[beg + i + 3]);
        float2 v0 = __half22float2(yb[(size_t)s0 * 32 + lane]);
        float2 v1 = __half22float2(yb[(size_t)s1 * 32 + lane]);
        float2 v2 = __half22float2(yb[(size_t)s2 * 32 + lane]);
        float2 v3 = __half22float2(yb[(size_t)s3 * 32 + lane]);
        acc.x += (v0.x + v1.x) + (v2.x + v3.x);
        acc.y += (v0.y + v1.y) + (v2.y + v3.y);
    }
    for (; i < cnt; i++) {
        int s0 = __ldg(&g_srcs[beg + i]);
        float2 v0 = __half22float2(yb[(size_t)s0 * 32 + lane]);
        acc.x += v0.x;
        acc.y += v0.y;
    }

    float dv = g_dinv[node];
    float hx = fmaxf(fmaf(acc.x, dv, __ldg(&bias[lane * 2])), 0.f);
    float hy = fmaxf(fmaf(acc.y, dv, __ldg(&bias[lane * 2 + 1])), 0.f);

    if (!FINAL) {
        *(float2*)(g_h + (size_t)node * 64 + lane * 2) = make_float2(hx, hy);
    } else {
        float v = hx * __ldg(&Wfc[lane * 2]) + hy * __ldg(&Wfc[lane * 2 + 1]);
        #pragma unroll
        for (int o = 16; o; o >>= 1)
            v += __shfl_down_sync(0xffffffffu, v, o);
        if (lane == 0) {
            float z = v + __ldg(&bfc[0]);
            out[node] = 1.0f / (1.0f + expf(-z));
        }
    }
}

// ---------------- launch ----------------------------------------------------
extern "C" void kernel_launch(void* const* d_in, const int* in_sizes, int n_in,
                              void* d_out, int out_size) {
    const float* x   = (const float*)d_in[0];
    const void*  ei  = d_in[1];
    const float* W1  = (const float*)d_in[2];
    const float* b1  = (const float*)d_in[3];
    const float* W2  = (const float*)d_in[4];
    const float* b2  = (const float*)d_in[5];
    const float* Wfc = (const float*)d_in[6];
    const float* bfc = (const float*)d_in[7];
    float* out = (float*)d_out;

    int N = in_sizes[0] / 128;
    int E = in_sizes[1] / 2;
    if (N > MAXN) N = MAXN;
    if (E > MAXE) E = MAXE;

    const int TB = 256;
    int nb_N  = (N + TB - 1) / TB;
    int nb_E  = (E + TB - 1) / TB;
    int nb_GM = (N + 63) / 64;
    int nb_AG = (N + 7) / 8;
    int nblk  = (N + SCAN_TILE - 1) / SCAN_TILE;
    int nb_P3 = (N + TB * 4 - 1) / (TB * 4);

    detect_kernel<<<1, 32>>>((const int*)ei);
    zero_deg<<<nb_N, TB>>>(N);
    convert_kernel<<<nb_E, TB>>>(ei, E);
    scan_pass1<<<nblk, 1024>>>(N);
    scan_pass2<<<1, 64>>>(nblk);
    scan_pass3<<<nb_P3, TB>>>(N);
    place_kernel<<<nb_E, TB>>>(E);
    dinv_kernel<<<nb_N, TB>>>(N);

    // layer 1
    gemm_scale<128, false><<<nb_GM, 256>>>(x, W1, N);
    aggregate_kernel<false><<<nb_AG, 256>>>(b1, nullptr, nullptr, nullptr, N);

    // layer 2
    gemm_scale<64, true><<<nb_GM, 256>>>(nullptr, W2, N);
    aggregate_kernel<true><<<nb_AG, 256>>>(b2, Wfc, bfc, out, N);
}

// round 6
// speedup vs baseline: 1.1757x; 1.0350x over previous
#include <cuda_runtime.h>
#include <cuda_fp16.h>
#include <math.h>

#define MAXN 100000
#define MAXE 1600000
#define HDIM 64
#define SCAN_TILE 4096

// ---------------- device scratch (no allocations allowed) ----------------
__device__ int    g_is64;
__device__ int    g_row [MAXE];
__device__ int    g_cole[MAXE];
__device__ int    g_srcs[MAXE];
__device__ int    g_degi[MAXN];
__device__ int    g_off [MAXN];
__device__ int    g_cur [MAXN];
__device__ int    g_bsum[64];
__device__ float  g_dinv[MAXN];
__device__ __half g_yh[(size_t)MAXN * HDIM];   // dinv-scaled xW, fp16
__device__ float  g_h [(size_t)MAXN * HDIM];   // layer activations, fp32

// ---------------- dtype detection (int32 vs int64 edge_index) ------------
__global__ void detect_kernel(const int* __restrict__ ei) {
    if (threadIdx.x == 0 && blockIdx.x == 0) {
        int is64 = 1;
        for (int i = 1; i < 128; i += 2)
            if (ei[i] != 0) { is64 = 0; break; }
        g_is64 = is64;
    }
}

__global__ void zero_deg(int N) {
    int i = blockIdx.x * blockDim.x + threadIdx.x;
    if (i < N) g_degi[i] = 0;
}

__global__ void convert_kernel(const void* __restrict__ ei, int E) {
    int e = blockIdx.x * blockDim.x + threadIdx.x;
    if (e >= E) return;
    int r, c;
    if (g_is64) {
        const long long* p = (const long long*)ei;
        r = (int)p[e]; c = (int)p[e + E];
    } else {
        const int* p = (const int*)ei;
        r = p[e]; c = p[e + E];
    }
    g_row[e] = r;
    g_cole[e] = c;
    atomicAdd(&g_degi[c], 1);
}

// ---------------- multi-block exclusive scan ------------------------------
__global__ void scan_pass1(int N) {
    __shared__ int warpsum[32];
    int lane = threadIdx.x & 31, wid = threadIdx.x >> 5;
    int idx = blockIdx.x * SCAN_TILE + threadIdx.x * 4;

    int4 v = make_int4(0, 0, 0, 0);
    if (idx + 3 < N) v = *(const int4*)(g_degi + idx);
    else {
        if (idx     < N) v.x = g_degi[idx];
        if (idx + 1 < N) v.y = g_degi[idx + 1];
        if (idx + 2 < N) v.z = g_degi[idx + 2];
        if (idx + 3 < N) v.w = g_degi[idx + 3];
    }
    int s0 = v.x, s1 = s0 + v.y, s2 = s1 + v.z, s3 = s2 + v.w;
    int sc = s3;
    #pragma unroll
    for (int o = 1; o < 32; o <<= 1) {
        int t = __shfl_up_sync(0xffffffffu, sc, o);
        if (lane >= o) sc += t;
    }
    if (lane == 31) warpsum[wid] = sc;
    __syncthreads();
    if (wid == 0) {
        int ws = warpsum[lane];
        int wsc = ws;
        #pragma unroll
        for (int o = 1; o < 32; o <<= 1) {
            int t = __shfl_up_sync(0xffffffffu, wsc, o);
            if (lane >= o) wsc += t;
        }
        warpsum[lane] = wsc - ws;
        if (lane == 31) g_bsum[blockIdx.x] = wsc;
    }
    __syncthreads();
    int carry = warpsum[wid] + (sc - s3);
    if (idx     < N) g_off[idx]     = carry;
    if (idx + 1 < N) g_off[idx + 1] = carry + s0;
    if (idx + 2 < N) g_off[idx + 2] = carry + s1;
    if (idx + 3 < N) g_off[idx + 3] = carry + s2;
}

__global__ void scan_pass2(int nblk) {
    int lane = threadIdx.x;  // 64 threads
    __shared__ int sh[64];
    int v = (lane < nblk) ? g_bsum[lane] : 0;
    sh[lane] = v;
    __syncthreads();
    int acc = v;
    for (int o = 1; o < 64; o <<= 1) {
        int t = (lane >= o) ? sh[lane - o] : 0;
        __syncthreads();
        acc += t;
        sh[lane] = acc;
        __syncthreads();
    }
    if (lane < nblk) g_bsum[lane] = acc - v;
}

__global__ void scan_pass3(int N) {
    int idx = (blockIdx.x * blockDim.x + threadIdx.x) * 4;
    if (idx >= N) return;
    int add = g_bsum[idx / SCAN_TILE];
    if (idx + 3 < N) {
        int4 v = *(const int4*)(g_off + idx);
        v.x += add; v.y += add; v.z += add; v.w += add;
        *(int4*)(g_off + idx) = v;
        *(int4*)(g_cur + idx) = v;
    } else {
        for (int k = 0; k < 4 && idx + k < N; k++) {
            int v = g_off[idx + k] + add;
            g_off[idx + k] = v;
            g_cur[idx + k] = v;
        }
    }
}

__global__ void place_kernel(int E) {
    int e = blockIdx.x * blockDim.x + threadIdx.x;
    if (e >= E) return;
    int c = g_cole[e];
    int pos = atomicAdd(&g_cur[c], 1);
    g_srcs[pos] = g_row[e];
}

__global__ void dinv_kernel(int N) {
    int i = blockIdx.x * blockDim.x + threadIdx.x;
    if (i < N) g_dinv[i] = rsqrtf((float)(g_degi[i] + 1));
}

// ---------------- GEMM: Yh = fp16((X @ W) * dinv) --------------------------
// Proven shape: X [N,K] row-major, W [K,64]. Block 64x64, 256 threads, 4x4.
template<int K, bool X_FROM_GH>
__global__ void gemm_scale(const float* __restrict__ Xin,
                           const float* __restrict__ W, int N) {
    const float* __restrict__ X = X_FROM_GH ? g_h : Xin;
    __shared__ float Xs[16][64];
    __shared__ float Ws[16][64];

    int tid = threadIdx.x;
    int ty = tid >> 4;
    int tx = tid & 15;
    int row0 = blockIdx.x * 64;

    float acc[4][4] = {};

    int lr  = tid >> 2;
    int lkq = (tid & 3) << 2;
    int wkr = tid >> 4;
    int wcq = (tid & 15) << 2;

    for (int kc = 0; kc < K; kc += 16) {
        float4 xv = make_float4(0.f, 0.f, 0.f, 0.f);
        int grow = row0 + lr;
        if (grow < N)
            xv = *(const float4*)(X + (size_t)grow * K + kc + lkq);
        Xs[lkq + 0][lr] = xv.x;
        Xs[lkq + 1][lr] = xv.y;
        Xs[lkq + 2][lr] = xv.z;
        Xs[lkq + 3][lr] = xv.w;

        *(float4*)&Ws[wkr][wcq] =
            *(const float4*)(W + (size_t)(kc + wkr) * 64 + wcq);
        __syncthreads();

        #pragma unroll
        for (int k = 0; k < 16; k++) {
            float4 a = *(const float4*)&Xs[k][ty << 2];
            float4 b = *(const float4*)&Ws[k][tx << 2];
            float av[4] = {a.x, a.y, a.z, a.w};
            float bv[4] = {b.x, b.y, b.z, b.w};
            #pragma unroll
            for (int i = 0; i < 4; i++)
                #pragma unroll
                for (int j = 0; j < 4; j++)
                    acc[i][j] = fmaf(av[i], bv[j], acc[i][j]);
        }
        __syncthreads();
    }

    #pragma unroll
    for (int i = 0; i < 4; i++) {
        int r = row0 + (ty << 2) + i;
        if (r < N) {
            float s = g_dinv[r];
            __half2 p0 = __floats2half2_rn(acc[i][0] * s, acc[i][1] * s);
            __half2 p1 = __floats2half2_rn(acc[i][2] * s, acc[i][3] * s);
            *(uint2*)(g_yh + (size_t)r * 64 + (tx << 2)) =
                make_uint2(*(unsigned*)&p0, *(unsigned*)&p1);
        }
    }
}

// ---------------- aggregation: warp per node, 2 edges per LDG --------------
// Half-warp A (lanes 0-15) handles even CSR slots, half B odd slots.
// Each lane loads 8B (4 halves) of its edge's row: one LDG.64 per warp covers
// two edges. Halves combined at the end via shfl_xor(16).
template<bool FINAL>
__global__ void aggregate_kernel(const float* __restrict__ bias,
                                 const float* __restrict__ Wfc,
                                 const float* __restrict__ bfc,
                                 float* __restrict__ out, int N) {
    int node = blockIdx.x * 8 + (threadIdx.x >> 5);
    if (node >= N) return;
    int lane = threadIdx.x & 31;
    int half_id = lane >> 4;     // 0: even slots, 1: odd slots
    int sub = lane & 15;         // covers halves [sub*4, sub*4+4)

    int beg = g_off[node];
    int cnt = g_degi[node];

    float4 acc = make_float4(0.f, 0.f, 0.f, 0.f);

    // self loop (count once: half A only)
    if (half_id == 0) {
        uint2 sv = *(const uint2*)(g_yh + (size_t)node * 64 + sub * 4);
        float2 f0 = __half22float2(*(__half2*)&sv.x);
        float2 f1 = __half22float2(*(__half2*)&sv.y);
        acc = make_float4(f0.x, f0.y, f1.x, f1.y);
    }

    int m = (cnt - half_id + 1) >> 1;          // edges for this half
    const int* sp = g_srcs + beg + half_id;    // stride-2 walk

    int j = 0;
    for (; j + 1 < m; j += 2) {
        int s0 = __ldg(sp + 2 * j);
        int s1 = __ldg(sp + 2 * j + 2);
        uint2 v0 = *(const uint2*)(g_yh + (size_t)s0 * 64 + sub * 4);
        uint2 v1 = *(const uint2*)(g_yh + (size_t)s1 * 64 + sub * 4);
        float2 a0 = __half22float2(*(__half2*)&v0.x);
        float2 a1 = __half22float2(*(__half2*)&v0.y);
        float2 b0 = __half22float2(*(__half2*)&v1.x);
        float2 b1 = __half22float2(*(__half2*)&v1.y);
        acc.x += a0.x + b0.x;
        acc.y += a0.y + b0.y;
        acc.z += a1.x + b1.x;
        acc.w += a1.y + b1.y;
    }
    if (j < m) {
        int s0 = __ldg(sp + 2 * j);
        uint2 v0 = *(const uint2*)(g_yh + (size_t)s0 * 64 + sub * 4);
        float2 a0 = __half22float2(*(__half2*)&v0.x);
        float2 a1 = __half22float2(*(__half2*)&v0.y);
        acc.x += a0.x;
        acc.y += a0.y;
        acc.z += a1.x;
        acc.w += a1.y;
    }

    // combine half-warps (both halves end with identical sums)
    acc.x += __shfl_xor_sync(0xffffffffu, acc.x, 16);
    acc.y += __shfl_xor_sync(0xffffffffu, acc.y, 16);
    acc.z += __shfl_xor_sync(0xffffffffu, acc.z, 16);
    acc.w += __shfl_xor_sync(0xffffffffu, acc.w, 16);

    float dv = g_dinv[node];
    float4 bb = *(const float4*)(bias + sub * 4);
    float h0 = fmaxf(fmaf(acc.x, dv, bb.x), 0.f);
    float h1 = fmaxf(fmaf(acc.y, dv, bb.y), 0.f);
    float h2 = fmaxf(fmaf(acc.z, dv, bb.z), 0.f);
    float h3 = fmaxf(fmaf(acc.w, dv, bb.w), 0.f);

    if (!FINAL) {
        if (half_id == 0)
            *(float4*)(g_h + (size_t)node * 64 + sub * 4) =
                make_float4(h0, h1, h2, h3);
    } else {
        float v = 0.f;
        if (half_id == 0) {
            float4 w = *(const float4*)(Wfc + sub * 4);
            v = h0 * w.x + h1 * w.y + h2 * w.z + h3 * w.w;
        }
        #pragma unroll
        for (int o = 16; o; o >>= 1)
            v += __shfl_down_sync(0xffffffffu, v, o);
        if (lane == 0) {
            float z = v + __ldg(&bfc[0]);
            out[node] = 1.0f / (1.0f + expf(-z));
        }
    }
}

// ---------------- launch ----------------------------------------------------
extern "C" void kernel_launch(void* const* d_in, const int* in_sizes, int n_in,
                              void* d_out, int out_size) {
    const float* x   = (const float*)d_in[0];
    const void*  ei  = d_in[1];
    const float* W1  = (const float*)d_in[2];
    const float* b1  = (const float*)d_in[3];
    const float* W2  = (const float*)d_in[4];
    const float* b2  = (const float*)d_in[5];
    const float* Wfc = (const float*)d_in[6];
    const float* bfc = (const float*)d_in[7];
    float* out = (float*)d_out;

    int N = in_sizes[0] / 128;
    int E = in_sizes[1] / 2;
    if (N > MAXN) N = MAXN;
    if (E > MAXE) E = MAXE;

    const int TB = 256;
    int nb_N  = (N + TB - 1) / TB;
    int nb_E  = (E + TB - 1) / TB;
    int nb_GM = (N + 63) / 64;
    int nb_AG = (N + 7) / 8;
    int nblk  = (N + SCAN_TILE - 1) / SCAN_TILE;
    int nb_P3 = (N + TB * 4 - 1) / (TB * 4);

    detect_kernel<<<1, 32>>>((const int*)ei);
    zero_deg<<<nb_N, TB>>>(N);
    convert_kernel<<<nb_E, TB>>>(ei, E);
    scan_pass1<<<nblk, 1024>>>(N);
    scan_pass2<<<1, 64>>>(nblk);
    scan_pass3<<<nb_P3, TB>>>(N);
    place_kernel<<<nb_E, TB>>>(E);
    dinv_kernel<<<nb_N, TB>>>(N);

    // layer 1
    gemm_scale<128, false><<<nb_GM, 256>>>(x, W1, N);
    aggregate_kernel<false><<<nb_AG, 256>>>(b1, nullptr, nullptr, nullptr, N);

    // layer 2
    gemm_scale<64, true><<<nb_GM, 256>>>(nullptr, W2, N);
    aggregate_kernel<true><<<nb_AG, 256>>>(b2, Wfc, bfc, out, N);
}

// round 8
// speedup vs baseline: 1.4233x; 1.2106x over previous
#include <cuda_runtime.h>
#include <cuda_fp16.h>
#include <stdint.h>
#include <math.h>

#define MAXN 100000
#define MAXE 1600000
#define HDIM 64
#define SCAN_TILE 4096

// ---------------- device scratch (no allocations allowed) ----------------
__device__ int    g_is64;
__device__ int    g_row [MAXE];
__device__ int    g_cole[MAXE];
__device__ int    g_srcs[MAXE];
__device__ int    g_degi[MAXN];
__device__ int    g_off [MAXN];
__device__ int    g_cur [MAXN];
__device__ int    g_bsum[64];
__device__ float  g_dinv[MAXN];
__device__ __half g_yh[(size_t)MAXN * HDIM];   // dinv-scaled xW, fp16
__device__ __half g_h [(size_t)MAXN * HDIM];   // layer activations, fp16

// ---------------- dtype detection (int32 vs int64 edge_index) ------------
__global__ void detect_kernel(const int* __restrict__ ei) {
    if (threadIdx.x == 0 && blockIdx.x == 0) {
        int is64 = 1;
        for (int i = 1; i < 128; i += 2)
            if (ei[i] != 0) { is64 = 0; break; }
        g_is64 = is64;
    }
}

__global__ void zero_deg(int N) {
    int i = blockIdx.x * blockDim.x + threadIdx.x;
    if (i < N) g_degi[i] = 0;
}

__global__ void convert_kernel(const void* __restrict__ ei, int E) {
    int e = blockIdx.x * blockDim.x + threadIdx.x;
    if (e >= E) return;
    int r, c;
    if (g_is64) {
        const long long* p = (const long long*)ei;
        r = (int)p[e]; c = (int)p[e + E];
    } else {
        const int* p = (const int*)ei;
        r = p[e]; c = p[e + E];
    }
    g_row[e] = r;
    g_cole[e] = c;
    atomicAdd(&g_degi[c], 1);
}

// ---------------- multi-block exclusive scan ------------------------------
__global__ void scan_pass1(int N) {
    __shared__ int warpsum[32];
    int lane = threadIdx.x & 31, wid = threadIdx.x >> 5;
    int idx = blockIdx.x * SCAN_TILE + threadIdx.x * 4;

    int4 v = make_int4(0, 0, 0, 0);
    if (idx + 3 < N) v = *(const int4*)(g_degi + idx);
    else {
        if (idx     < N) v.x = g_degi[idx];
        if (idx + 1 < N) v.y = g_degi[idx + 1];
        if (idx + 2 < N) v.z = g_degi[idx + 2];
        if (idx + 3 < N) v.w = g_degi[idx + 3];
    }
    int s0 = v.x, s1 = s0 + v.y, s2 = s1 + v.z, s3 = s2 + v.w;
    int sc = s3;
    #pragma unroll
    for (int o = 1; o < 32; o <<= 1) {
        int t = __shfl_up_sync(0xffffffffu, sc, o);
        if (lane >= o) sc += t;
    }
    if (lane == 31) warpsum[wid] = sc;
    __syncthreads();
    if (wid == 0) {
        int ws = warpsum[lane];
        int wsc = ws;
        #pragma unroll
        for (int o = 1; o < 32; o <<= 1) {
            int t = __shfl_up_sync(0xffffffffu, wsc, o);
            if (lane >= o) wsc += t;
        }
        warpsum[lane] = wsc - ws;
        if (lane == 31) g_bsum[blockIdx.x] = wsc;
    }
    __syncthreads();
    int carry = warpsum[wid] + (sc - s3);
    if (idx     < N) g_off[idx]     = carry;
    if (idx + 1 < N) g_off[idx + 1] = carry + s0;
    if (idx + 2 < N) g_off[idx + 2] = carry + s1;
    if (idx + 3 < N) g_off[idx + 3] = carry + s2;
}

__global__ void scan_pass2(int nblk) {
    int lane = threadIdx.x;  // 64 threads
    __shared__ int sh[64];
    int v = (lane < nblk) ? g_bsum[lane] : 0;
    sh[lane] = v;
    __syncthreads();
    int acc = v;
    for (int o = 1; o < 64; o <<= 1) {
        int t = (lane >= o) ? sh[lane - o] : 0;
        __syncthreads();
        acc += t;
        sh[lane] = acc;
        __syncthreads();
    }
    if (lane < nblk) g_bsum[lane] = acc - v;
}

__global__ void scan_pass3(int N) {
    int idx = (blockIdx.x * blockDim.x + threadIdx.x) * 4;
    if (idx >= N) return;
    int add = g_bsum[idx / SCAN_TILE];
    if (idx + 3 < N) {
        int4 v = *(const int4*)(g_off + idx);
        v.x += add; v.y += add; v.z += add; v.w += add;
        *(int4*)(g_off + idx) = v;
        *(int4*)(g_cur + idx) = v;
    } else {
        for (int k = 0; k < 4 && idx + k < N; k++) {
            int v = g_off[idx + k] + add;
            g_off[idx + k] = v;
            g_cur[idx + k] = v;
        }
    }
}

__global__ void place_kernel(int E) {
    int e = blockIdx.x * blockDim.x + threadIdx.x;
    if (e >= E) return;
    int c = g_cole[e];
    int pos = atomicAdd(&g_cur[c], 1);
    g_srcs[pos] = g_row[e];
}

__global__ void dinv_kernel(int N) {
    int i = blockIdx.x * blockDim.x + threadIdx.x;
    if (i < N) g_dinv[i] = rsqrtf((float)(g_degi[i] + 1));
}

// ---------------- tensor-core GEMM: Yh = fp16((X @ W) * dinv) --------------
// mma.m16n8k16 fp16 in / fp32 acc. CTA tile 128x64, 256 threads (8 warps),
// warp w covers rows [w*16, w*16+16), all 64 cols (8 n-tiles of 8).
// Smem stride 72 halves => fragment LDS bank = (4r+c) mod 32, conflict-free.
template<int K, bool XHALF>
__global__ void __launch_bounds__(256)
gemm_mma(const float* __restrict__ Xf, const float* __restrict__ Wf, int N) {
    constexpr int KC = 64;
    constexpr int NSTEP = K / KC;
    constexpr int STRIDE = 72;  // halves
    __shared__ __half Xs[128 * STRIDE];
    __shared__ __half Wt[64 * STRIDE];   // Wt[n][k] = W[kc+k][n]

    int tid = threadIdx.x;
    int warp = tid >> 5, lane = tid & 31;
    int row0 = blockIdx.x * 128;
    int wrow = warp * 16;
    int r = lane >> 2;   // 0..7
    int c = lane & 3;    // 0..3

    float acc[8][4] = {};

    for (int s = 0; s < NSTEP; s++) {
        int kc = s * KC;
        if (!XHALF) {
            // X fp32 [N][K]: 128 rows x 64 cols chunk, convert to fp16
            for (int i = tid; i < 128 * 16; i += 256) {
                int rr = i >> 4, c4 = i & 15;
                int grow = row0 + rr;
                float4 v = make_float4(0.f, 0.f, 0.f, 0.f);
                if (grow < N)
                    v = *(const float4*)(Xf + (size_t)grow * K + kc + c4 * 4);
                *(__half2*)&Xs[rr * STRIDE + c4 * 4]     = __floats2half2_rn(v.x, v.y);
                *(__half2*)&Xs[rr * STRIDE + c4 * 4 + 2] = __floats2half2_rn(v.z, v.w);
            }
        } else {
            // X fp16 from g_h [N][64]
            for (int i = tid; i < 128 * 16; i += 256) {
                int rr = i >> 4, c4 = i & 15;
                int grow = row0 + rr;
                uint2 v = make_uint2(0u, 0u);
                if (grow < N)
                    v = *(const uint2*)(g_h + (size_t)grow * 64 + c4 * 4);
                *(uint2*)&Xs[rr * STRIDE + c4 * 4] = v;
            }
        }
        // W chunk transposed: Wt[n][k] = W[kc+k][n]
        for (int i = tid; i < KC * 64; i += 256) {
            int kk = i >> 6, nn = i & 63;
            Wt[nn * STRIDE + kk] = __float2half_rn(Wf[(size_t)(kc + kk) * 64 + nn]);
        }
        __syncthreads();

        #pragma unroll
        for (int ks = 0; ks < KC / 16; ks++) {
            int k0 = ks * 16;
            uint32_t a0 = *(const uint32_t*)&Xs[(wrow + r)     * STRIDE + k0 + 2 * c];
            uint32_t a1 = *(const uint32_t*)&Xs[(wrow + r + 8) * STRIDE + k0 + 2 * c];
            uint32_t a2 = *(const uint32_t*)&Xs[(wrow + r)     * STRIDE + k0 + 2 * c + 8];
            uint32_t a3 = *(const uint32_t*)&Xs[(wrow + r + 8) * STRIDE + k0 + 2 * c + 8];
            #pragma unroll
            for (int j = 0; j < 8; j++) {
                uint32_t b0 = *(const uint32_t*)&Wt[(j * 8 + r) * STRIDE + k0 + 2 * c];
                uint32_t b1 = *(const uint32_t*)&Wt[(j * 8 + r) * STRIDE + k0 + 2 * c + 8];
                asm volatile(
                    "mma.sync.aligned.m16n8k16.row.col.f32.f16.f16.f32 "
                    "{%0,%1,%2,%3}, {%4,%5,%6,%7}, {%8,%9}, {%0,%1,%2,%3};"
                    : "+f"(acc[j][0]), "+f"(acc[j][1]),
                      "+f"(acc[j][2]), "+f"(acc[j][3])
                    : "r"(a0), "r"(a1), "r"(a2), "r"(a3), "r"(b0), "r"(b1));
            }
        }
        __syncthreads();
    }

    // epilogue: scale by dinv, write fp16
    int gr0 = row0 + wrow + r;
    int gr1 = gr0 + 8;
    float d0 = (gr0 < N) ? g_dinv[gr0] : 0.f;
    float d1 = (gr1 < N) ? g_dinv[gr1] : 0.f;
    #pragma unroll
    for (int j = 0; j < 8; j++) {
        int col = j * 8 + 2 * c;
        if (gr0 < N)
            *(__half2*)&g_yh[(size_t)gr0 * 64 + col] =
                __floats2half2_rn(acc[j][0] * d0, acc[j][1] * d0);
        if (gr1 < N)
            *(__half2*)&g_yh[(size_t)gr1 * 64 + col] =
                __floats2half2_rn(acc[j][2] * d1, acc[j][3] * d1);
    }
}

// ---------------- aggregation: warp per node, 2 edges per LDG --------------
template<bool FINAL>
__global__ void aggregate_kernel(const float* __restrict__ bias,
                                 const float* __restrict__ Wfc,
                                 const float* __restrict__ bfc,
                                 float* __restrict__ out, int N) {
    int node = blockIdx.x * 8 + (threadIdx.x >> 5);
    if (node >= N) return;
    int lane = threadIdx.x & 31;
    int half_id = lane >> 4;
    int sub = lane & 15;

    int beg = g_off[node];
    int cnt = g_degi[node];

    float4 acc = make_float4(0.f, 0.f, 0.f, 0.f);

    if (half_id == 0) {
        uint2 sv = *(const uint2*)(g_yh + (size_t)node * 64 + sub * 4);
        float2 f0 = __half22float2(*(__half2*)&sv.x);
        float2 f1 = __half22float2(*(__half2*)&sv.y);
        acc = make_float4(f0.x, f0.y, f1.x, f1.y);
    }

    int m = (cnt - half_id + 1) >> 1;
    const int* sp = g_srcs + beg + half_id;

    int j = 0;
    for (; j + 1 < m; j += 2) {
        int s0 = __ldg(sp + 2 * j);
        int s1 = __ldg(sp + 2 * j + 2);
        uint2 v0 = *(const uint2*)(g_yh + (size_t)s0 * 64 + sub * 4);
        uint2 v1 = *(const uint2*)(g_yh + (size_t)s1 * 64 + sub * 4);
        float2 a0 = __half22float2(*(__half2*)&v0.x);
        float2 a1 = __half22float2(*(__half2*)&v0.y);
        float2 b0 = __half22float2(*(__half2*)&v1.x);
        float2 b1 = __half22float2(*(__half2*)&v1.y);
        acc.x += a0.x + b0.x;
        acc.y += a0.y + b0.y;
        acc.z += a1.x + b1.x;
        acc.w += a1.y + b1.y;
    }
    if (j < m) {
        int s0 = __ldg(sp + 2 * j);
        uint2 v0 = *(const uint2*)(g_yh + (size_t)s0 * 64 + sub * 4);
        float2 a0 = __half22float2(*(__half2*)&v0.x);
        float2 a1 = __half22float2(*(__half2*)&v0.y);
        acc.x += a0.x;
        acc.y += a0.y;
        acc.z += a1.x;
        acc.w += a1.y;
    }

    acc.x += __shfl_xor_sync(0xffffffffu, acc.x, 16);
    acc.y += __shfl_xor_sync(0xffffffffu, acc.y, 16);
    acc.z += __shfl_xor_sync(0xffffffffu, acc.z, 16);
    acc.w += __shfl_xor_sync(0xffffffffu, acc.w, 16);

    float dv = g_dinv[node];
    float4 bb = *(const float4*)(bias + sub * 4);
    float h0 = fmaxf(fmaf(acc.x, dv, bb.x), 0.f);
    float h1 = fmaxf(fmaf(acc.y, dv, bb.y), 0.f);
    float h2 = fmaxf(fmaf(acc.z, dv, bb.z), 0.f);
    float h3 = fmaxf(fmaf(acc.w, dv, bb.w), 0.f);

    if (!FINAL) {
        if (half_id == 0) {
            __half2 p0 = __floats2half2_rn(h0, h1);
            __half2 p1 = __floats2half2_rn(h2, h3);
            *(uint2*)(g_h + (size_t)node * 64 + sub * 4) =
                make_uint2(*(uint32_t*)&p0, *(uint32_t*)&p1);
        }
    } else {
        float v = 0.f;
        if (half_id == 0) {
            float4 w = *(const float4*)(Wfc + sub * 4);
            v = h0 * w.x + h1 * w.y + h2 * w.z + h3 * w.w;
        }
        #pragma unroll
        for (int o = 16; o; o >>= 1)
            v += __shfl_down_sync(0xffffffffu, v, o);
        if (lane == 0) {
            float z = v + __ldg(&bfc[0]);
            out[node] = 1.0f / (1.0f + expf(-z));
        }
    }
}

// ---------------- launch ----------------------------------------------------
extern "C" void kernel_launch(void* const* d_in, const int* in_sizes, int n_in,
                              void* d_out, int out_size) {
    const float* x   = (const float*)d_in[0];
    const void*  ei  = d_in[1];
    const float* W1  = (const float*)d_in[2];
    const float* b1  = (const float*)d_in[3];
    const float* W2  = (const float*)d_in[4];
    const float* b2  = (const float*)d_in[5];
    const float* Wfc = (const float*)d_in[6];
    const float* bfc = (const float*)d_in[7];
    float* out = (float*)d_out;

    int N = in_sizes[0] / 128;
    int E = in_sizes[1] / 2;
    if (N > MAXN) N = MAXN;
    if (E > MAXE) E = MAXE;

    const int TB = 256;
    int nb_N  = (N + TB - 1) / TB;
    int nb_E  = (E + TB - 1) / TB;
    int nb_GM = (N + 127) / 128;
    int nb_AG = (N + 7) / 8;
    int nblk  = (N + SCAN_TILE - 1) / SCAN_TILE;
    int nb_P3 = (N + TB * 4 - 1) / (TB * 4);

    detect_kernel<<<1, 32>>>((const int*)ei);
    zero_deg<<<nb_N, TB>>>(N);
    convert_kernel<<<nb_E, TB>>>(ei, E);
    scan_pass1<<<nblk, 1024>>>(N);
    scan_pass2<<<1, 64>>>(nblk);
    scan_pass3<<<nb_P3, TB>>>(N);
    place_kernel<<<nb_E, TB>>>(E);
    dinv_kernel<<<nb_N, TB>>>(N);

    // layer 1
    gemm_mma<128, false><<<nb_GM, 256>>>(x, W1, N);
    aggregate_kernel<false><<<nb_AG, 256>>>(b1, nullptr, nullptr, nullptr, N);

    // layer 2
    gemm_mma<64, true><<<nb_GM, 256>>>(nullptr, W2, N);
    aggregate_kernel<true><<<nb_AG, 256>>>(b2, Wfc, bfc, out, N);
}

// round 9
// speedup vs baseline: 1.4428x; 1.0137x over previous
#include <cuda_runtime.h>
#include <cuda_fp16.h>
#include <stdint.h>
#include <math.h>

#define MAXN 100000
#define MAXE 1600000
#define HDIM 64
#define SCAN_TILE 1024

// ---------------- device scratch (no allocations allowed) ----------------
__device__ int    g_is64;
__device__ int    g_srcs[MAXE];
__device__ int    g_degi[MAXN];
__device__ int    g_off [MAXN];
__device__ int    g_cur [MAXN];
__device__ int    g_bsum[128];
__device__ float  g_dinv[MAXN];
__device__ __half g_yh[(size_t)MAXN * HDIM];   // dinv-scaled xW, fp16
__device__ __half g_h [(size_t)MAXN * HDIM];   // layer activations, fp16

// ---------------- zero degrees + dtype detection ---------------------------
__global__ void zero_detect(const int* __restrict__ ei, int N) {
    int i = blockIdx.x * blockDim.x + threadIdx.x;
    if (i < N) g_degi[i] = 0;
    if (i == 0) {
        int is64 = 1;
        for (int t = 1; t < 128; t += 2)
            if (ei[t] != 0) { is64 = 0; break; }
        g_is64 = is64;
    }
}

// ---------------- degree histogram (reads edge_index directly) -------------
__global__ void deg_count(const void* __restrict__ ei, int E) {
    int e = blockIdx.x * blockDim.x + threadIdx.x;
    if (e >= E) return;
    int c;
    if (g_is64) c = (int)((const long long*)ei)[e + E];
    else        c = ((const int*)ei)[e + E];
    atomicAdd(&g_degi[c], 1);
}

// ---------------- multi-block exclusive scan (1024 elems/block) ------------
__global__ void scan_pass1(int N) {
    __shared__ int warpsum[8];
    int lane = threadIdx.x & 31, wid = threadIdx.x >> 5;
    int idx = blockIdx.x * SCAN_TILE + threadIdx.x * 4;

    int4 v = make_int4(0, 0, 0, 0);
    if (idx + 3 < N) v = *(const int4*)(g_degi + idx);
    else {
        if (idx     < N) v.x = g_degi[idx];
        if (idx + 1 < N) v.y = g_degi[idx + 1];
        if (idx + 2 < N) v.z = g_degi[idx + 2];
        if (idx + 3 < N) v.w = g_degi[idx + 3];
    }
    int s0 = v.x, s1 = s0 + v.y, s2 = s1 + v.z, s3 = s2 + v.w;
    int sc = s3;
    #pragma unroll
    for (int o = 1; o < 32; o <<= 1) {
        int t = __shfl_up_sync(0xffffffffu, sc, o);
        if (lane >= o) sc += t;
    }
    if (lane == 31) warpsum[wid] = sc;
    __syncthreads();
    if (wid == 0 && lane < 8) {
        int ws = warpsum[lane];
        int wsc = ws;
        #pragma unroll
        for (int o = 1; o < 8; o <<= 1) {
            int t = __shfl_up_sync(0xffu, wsc, o);
            if (lane >= o) wsc += t;
        }
        warpsum[lane] = wsc - ws;
        if (lane == 7) g_bsum[blockIdx.x] = wsc;
    }
    __syncthreads();
    int carry = warpsum[wid] + (sc - s3);
    if (idx     < N) g_off[idx]     = carry;
    if (idx + 1 < N) g_off[idx + 1] = carry + s0;
    if (idx + 2 < N) g_off[idx + 2] = carry + s1;
    if (idx + 3 < N) g_off[idx + 3] = carry + s2;
}

__global__ void scan_pass2(int nblk) {
    int lane = threadIdx.x;  // 128 threads
    __shared__ int sh[128];
    int v = (lane < nblk) ? g_bsum[lane] : 0;
    sh[lane] = v;
    __syncthreads();
    int acc = v;
    for (int o = 1; o < 128; o <<= 1) {
        int t = (lane >= o) ? sh[lane - o] : 0;
        __syncthreads();
        acc += t;
        sh[lane] = acc;
        __syncthreads();
    }
    if (lane < nblk) g_bsum[lane] = acc - v;
}

// pass 3: add block offsets, init cursors, compute dinv
__global__ void scan_pass3(int N) {
    int idx = (blockIdx.x * blockDim.x + threadIdx.x) * 4;
    if (idx >= N) return;
    int add = g_bsum[idx / SCAN_TILE];
    #pragma unroll
    for (int k = 0; k < 4; k++) {
        if (idx + k < N) {
            int v = g_off[idx + k] + add;
            g_off[idx + k] = v;
            g_cur[idx + k] = v;
            g_dinv[idx + k] = rsqrtf((float)(g_degi[idx + k] + 1));
        }
    }
}

// place sources into CSR slots (reads edge_index directly)
__global__ void place_kernel(const void* __restrict__ ei, int E) {
    int e = blockIdx.x * blockDim.x + threadIdx.x;
    if (e >= E) return;
    int r, c;
    if (g_is64) {
        const long long* p = (const long long*)ei;
        r = (int)p[e]; c = (int)p[e + E];
    } else {
        const int* p = (const int*)ei;
        r = p[e]; c = p[e + E];
    }
    int pos = atomicAdd(&g_cur[c], 1);
    g_srcs[pos] = r;
}

// ---------------- tensor-core GEMM: Yh = fp16((X @ W) * dinv) --------------
template<int K, bool XHALF>
__global__ void __launch_bounds__(256)
gemm_mma(const float* __restrict__ Xf, const float* __restrict__ Wf, int N) {
    constexpr int KC = 64;
    constexpr int NSTEP = K / KC;
    constexpr int STRIDE = 72;  // halves
    __shared__ __half Xs[128 * STRIDE];
    __shared__ __half Wt[64 * STRIDE];   // Wt[n][k] = W[kc+k][n]

    int tid = threadIdx.x;
    int warp = tid >> 5, lane = tid & 31;
    int row0 = blockIdx.x * 128;
    int wrow = warp * 16;
    int r = lane >> 2;   // 0..7
    int c = lane & 3;    // 0..3

    float acc[8][4] = {};

    for (int s = 0; s < NSTEP; s++) {
        int kc = s * KC;
        if (!XHALF) {
            for (int i = tid; i < 128 * 16; i += 256) {
                int rr = i >> 4, c4 = i & 15;
                int grow = row0 + rr;
                float4 v = make_float4(0.f, 0.f, 0.f, 0.f);
                if (grow < N)
                    v = *(const float4*)(Xf + (size_t)grow * K + kc + c4 * 4);
                *(__half2*)&Xs[rr * STRIDE + c4 * 4]     = __floats2half2_rn(v.x, v.y);
                *(__half2*)&Xs[rr * STRIDE + c4 * 4 + 2] = __floats2half2_rn(v.z, v.w);
            }
        } else {
            for (int i = tid; i < 128 * 16; i += 256) {
                int rr = i >> 4, c4 = i & 15;
                int grow = row0 + rr;
                uint2 v = make_uint2(0u, 0u);
                if (grow < N)
                    v = *(const uint2*)(g_h + (size_t)grow * 64 + c4 * 4);
                *(uint2*)&Xs[rr * STRIDE + c4 * 4] = v;
            }
        }
        for (int i = tid; i < KC * 64; i += 256) {
            int kk = i >> 6, nn = i & 63;
            Wt[nn * STRIDE + kk] = __float2half_rn(Wf[(size_t)(kc + kk) * 64 + nn]);
        }
        __syncthreads();

        #pragma unroll
        for (int ks = 0; ks < KC / 16; ks++) {
            int k0 = ks * 16;
            uint32_t a0 = *(const uint32_t*)&Xs[(wrow + r)     * STRIDE + k0 + 2 * c];
            uint32_t a1 = *(const uint32_t*)&Xs[(wrow + r + 8) * STRIDE + k0 + 2 * c];
            uint32_t a2 = *(const uint32_t*)&Xs[(wrow + r)     * STRIDE + k0 + 2 * c + 8];
            uint32_t a3 = *(const uint32_t*)&Xs[(wrow + r + 8) * STRIDE + k0 + 2 * c + 8];
            #pragma unroll
            for (int j = 0; j < 8; j++) {
                uint32_t b0 = *(const uint32_t*)&Wt[(j * 8 + r) * STRIDE + k0 + 2 * c];
                uint32_t b1 = *(const uint32_t*)&Wt[(j * 8 + r) * STRIDE + k0 + 2 * c + 8];
                asm volatile(
                    "mma.sync.aligned.m16n8k16.row.col.f32.f16.f16.f32 "
                    "{%0,%1,%2,%3}, {%4,%5,%6,%7}, {%8,%9}, {%0,%1,%2,%3};"
                    : "+f"(acc[j][0]), "+f"(acc[j][1]),
                      "+f"(acc[j][2]), "+f"(acc[j][3])
                    : "r"(a0), "r"(a1), "r"(a2), "r"(a3), "r"(b0), "r"(b1));
            }
        }
        __syncthreads();
    }

    int gr0 = row0 + wrow + r;
    int gr1 = gr0 + 8;
    float d0 = (gr0 < N) ? g_dinv[gr0] : 0.f;
    float d1 = (gr1 < N) ? g_dinv[gr1] : 0.f;
    #pragma unroll
    for (int j = 0; j < 8; j++) {
        int col = j * 8 + 2 * c;
        if (gr0 < N)
            *(__half2*)&g_yh[(size_t)gr0 * 64 + col] =
                __floats2half2_rn(acc[j][0] * d0, acc[j][1] * d0);
        if (gr1 < N)
            *(__half2*)&g_yh[(size_t)gr1 * 64 + col] =
                __floats2half2_rn(acc[j][2] * d1, acc[j][3] * d1);
    }
}

// ---------------- aggregation: warp per node, 4 edges per LDG --------------
// Quarter-warp q (8 lanes) handles CSR slots q, q+4, ...; each lane loads
// 16B (8 halves) so 8 lanes cover one 128B row; one LDG.128 instruction
// fetches 4 edges' rows. Quarters combined via shfl_xor(8), shfl_xor(16).
template<bool FINAL>
__global__ void aggregate_kernel(const float* __restrict__ bias,
                                 const float* __restrict__ Wfc,
                                 const float* __restrict__ bfc,
                                 float* __restrict__ out, int N) {
    int node = blockIdx.x * 8 + (threadIdx.x >> 5);
    if (node >= N) return;
    int lane = threadIdx.x & 31;
    int q = lane >> 3;       // quarter 0..3
    int sub = lane & 7;      // covers cols [sub*8, sub*8+8)

    int beg = g_off[node];
    int cnt = g_degi[node];

    float acc[8] = {};

    // self loop counted once (quarter 0)
    if (q == 0) {
        uint4 sv = *(const uint4*)(g_yh + (size_t)node * 64 + sub * 8);
        const __half2* hp = (const __half2*)&sv;
        #pragma unroll
        for (int t = 0; t < 4; t++) {
            float2 f = __half22float2(hp[t]);
            acc[2 * t]     = f.x;
            acc[2 * t + 1] = f.y;
        }
    }

    int m = (cnt - q + 3) >> 2;            // slots for this quarter
    const int* sp = g_srcs + beg + q;      // stride-4 walk

    int j = 0;
    for (; j + 1 < m; j += 2) {
        int s0 = __ldg(sp + 4 * j);
        int s1 = __ldg(sp + 4 * j + 4);
        uint4 v0 = *(const uint4*)(g_yh + (size_t)s0 * 64 + sub * 8);
        uint4 v1 = *(const uint4*)(g_yh + (size_t)s1 * 64 + sub * 8);
        const __half2* h0 = (const __half2*)&v0;
        const __half2* h1 = (const __half2*)&v1;
        #pragma unroll
        for (int t = 0; t < 4; t++) {
            float2 f0 = __half22float2(h0[t]);
            float2 f1 = __half22float2(h1[t]);
            acc[2 * t]     += f0.x + f1.x;
            acc[2 * t + 1] += f0.y + f1.y;
        }
    }
    if (j < m) {
        int s0 = __ldg(sp + 4 * j);
        uint4 v0 = *(const uint4*)(g_yh + (size_t)s0 * 64 + sub * 8);
        const __half2* h0 = (const __half2*)&v0;
        #pragma unroll
        for (int t = 0; t < 4; t++) {
            float2 f0 = __half22float2(h0[t]);
            acc[2 * t]     += f0.x;
            acc[2 * t + 1] += f0.y;
        }
    }

    // combine quarters: lanes {l, l^8, l^16, l^24} share sub
    #pragma unroll
    for (int t = 0; t < 8; t++) {
        acc[t] += __shfl_xor_sync(0xffffffffu, acc[t], 8);
        acc[t] += __shfl_xor_sync(0xffffffffu, acc[t], 16);
    }

    float dv = g_dinv[node];
    float4 bb0 = *(const float4*)(bias + sub * 8);
    float4 bb1 = *(const float4*)(bias + sub * 8 + 4);
    float h[8];
    h[0] = fmaxf(fmaf(acc[0], dv, bb0.x), 0.f);
    h[1] = fmaxf(fmaf(acc[1], dv, bb0.y), 0.f);
    h[2] = fmaxf(fmaf(acc[2], dv, bb0.z), 0.f);
    h[3] = fmaxf(fmaf(acc[3], dv, bb0.w), 0.f);
    h[4] = fmaxf(fmaf(acc[4], dv, bb1.x), 0.f);
    h[5] = fmaxf(fmaf(acc[5], dv, bb1.y), 0.f);
    h[6] = fmaxf(fmaf(acc[6], dv, bb1.z), 0.f);
    h[7] = fmaxf(fmaf(acc[7], dv, bb1.w), 0.f);

    if (!FINAL) {
        if (q == 0) {
            __half2 p[4];
            #pragma unroll
            for (int t = 0; t < 4; t++)
                p[t] = __floats2half2_rn(h[2 * t], h[2 * t + 1]);
            *(uint4*)(g_h + (size_t)node * 64 + sub * 8) = *(uint4*)p;
        }
    } else {
        float4 w0 = *(const float4*)(Wfc + sub * 8);
        float4 w1 = *(const float4*)(Wfc + sub * 8 + 4);
        float v = h[0] * w0.x + h[1] * w0.y + h[2] * w0.z + h[3] * w0.w
                + h[4] * w1.x + h[5] * w1.y + h[6] * w1.z + h[7] * w1.w;
        // all quarters hold identical per-sub sums; reduce over sub 0..7
        v += __shfl_down_sync(0xffffffffu, v, 4);
        v += __shfl_down_sync(0xffffffffu, v, 2);
        v += __shfl_down_sync(0xffffffffu, v, 1);
        if (lane == 0) {
            float z = v + __ldg(&bfc[0]);
            out[node] = 1.0f / (1.0f + expf(-z));
        }
    }
}

// ---------------- launch ----------------------------------------------------
extern "C" void kernel_launch(void* const* d_in, const int* in_sizes, int n_in,
                              void* d_out, int out_size) {
    const float* x   = (const float*)d_in[0];
    const void*  ei  = d_in[1];
    const float* W1  = (const float*)d_in[2];
    const float* b1  = (const float*)d_in[3];
    const float* W2  = (const float*)d_in[4];
    const float* b2  = (const float*)d_in[5];
    const float* Wfc = (const float*)d_in[6];
    const float* bfc = (const float*)d_in[7];
    float* out = (float*)d_out;

    int N = in_sizes[0] / 128;
    int E = in_sizes[1] / 2;
    if (N > MAXN) N = MAXN;
    if (E > MAXE) E = MAXE;

    const int TB = 256;
    int nb_N  = (N + TB - 1) / TB;
    int nb_E  = (E + TB - 1) / TB;
    int nb_GM = (N + 127) / 128;
    int nb_AG = (N + 7) / 8;
    int nblk  = (N + SCAN_TILE - 1) / SCAN_TILE;   // <= 98 for N<=100k
    int nb_P3 = (N + TB * 4 - 1) / (TB * 4);

    zero_detect<<<nb_N, TB>>>((const int*)ei, N);
    deg_count<<<nb_E, TB>>>(ei, E);
    scan_pass1<<<nblk, 256>>>(N);
    scan_pass2<<<1, 128>>>(nblk);
    scan_pass3<<<nb_P3, TB>>>(N);
    place_kernel<<<nb_E, TB>>>(ei, E);

    // layer 1
    gemm_mma<128, false><<<nb_GM, 256>>>(x, W1, N);
    aggregate_kernel<false><<<nb_AG, 256>>>(b1, nullptr, nullptr, nullptr, N);

    // layer 2
    gemm_mma<64, true><<<nb_GM, 256>>>(nullptr, W2, N);
    aggregate_kernel<true><<<nb_AG, 256>>>(b2, Wfc, bfc, out, N);
}